// round 1
// baseline (speedup 1.0000x reference)
#include <cuda_runtime.h>
#include <math.h>
#include <stdint.h>

// Problem constants
#define T_LEN 512
#define B_SZ  32
#define H_N   16
#define HD    64
#define D_EMB 1024
#define BH    512          // B_SZ * H_N
#define M_ROWS 16384       // T_LEN * B_SZ

// ---------------- device scratch (static: no allocations allowed) -----------
__device__ float g_Q[(size_t)T_LEN * BH * HD];   // [t][bh][hd], bh = b*16+h
__device__ float g_K[(size_t)T_LEN * BH * HD];
__device__ float g_V[(size_t)T_LEN * BH * HD];
__device__ float g_O[(size_t)T_LEN * BH * HD];   // attention output, = [t][b][1024]
__device__ float g_ATTN[(size_t)T_LEN * BH * BH]; // 512^3 floats = 536 MB

// ============================================================================
// GEMM: C[M,1024] = A @ W^T + bias.   W is [1024,1024] row-major (K contig).
// QMODE=1: A row m maps to query[b= m&31][t= m>>5]  (query is [B,T,D])
// QMODE=0: A row m is contiguous at A + m*1024
// Tiles: BM=128, BN=64, BK=16; 256 threads; 8x4 per thread.
// ============================================================================
template<int QMODE>
__global__ __launch_bounds__(256)
void gemm_nt_kernel(const float* __restrict__ A, const float* __restrict__ W,
                    const float* __restrict__ bias, float* __restrict__ C)
{
    __shared__ float As[16][132];   // [k][m] transposed, pitch 132 (16B aligned)
    __shared__ float Bs[16][68];    // [k][n]

    const int tid = threadIdx.x;
    const int m0 = blockIdx.y * 128;
    const int n0 = blockIdx.x * 64;
    const int tx = tid & 15;        // n-sub (4 cols)
    const int ty = tid >> 4;        // m-sub (8 rows)
    const int lrow = tid >> 2;      // 0..63 load row
    const int lkq  = (tid & 3) * 4; // k sub-offset 0,4,8,12

    float acc[8][4];
    #pragma unroll
    for (int i = 0; i < 8; i++)
        #pragma unroll
        for (int j = 0; j < 4; j++) acc[i][j] = 0.0f;

    for (int k0 = 0; k0 < 1024; k0 += 16) {
        // load A tile (128 rows x 16 k): each thread 2 float4
        #pragma unroll
        for (int rr = 0; rr < 2; rr++) {
            int row = lrow + rr * 64;
            int m = m0 + row;
            size_t aoff;
            if (QMODE) aoff = ((size_t)(m & 31) * 512 + (size_t)(m >> 5)) * 1024;
            else       aoff = (size_t)m * 1024;
            float4 v = *(const float4*)(A + aoff + k0 + lkq);
            As[lkq + 0][row] = v.x; As[lkq + 1][row] = v.y;
            As[lkq + 2][row] = v.z; As[lkq + 3][row] = v.w;
        }
        // load W tile (64 rows x 16 k): 1 float4 per thread
        {
            float4 v = *(const float4*)(W + (size_t)(n0 + lrow) * 1024 + k0 + lkq);
            Bs[lkq + 0][lrow] = v.x; Bs[lkq + 1][lrow] = v.y;
            Bs[lkq + 2][lrow] = v.z; Bs[lkq + 3][lrow] = v.w;
        }
        __syncthreads();

        #pragma unroll
        for (int k = 0; k < 16; k++) {
            float4 a0 = *(const float4*)&As[k][ty * 8];
            float4 a1 = *(const float4*)&As[k][ty * 8 + 4];
            float4 bv = *(const float4*)&Bs[k][tx * 4];
            float a[8] = {a0.x, a0.y, a0.z, a0.w, a1.x, a1.y, a1.z, a1.w};
            float b[4] = {bv.x, bv.y, bv.z, bv.w};
            #pragma unroll
            for (int i = 0; i < 8; i++)
                #pragma unroll
                for (int j = 0; j < 4; j++)
                    acc[i][j] += a[i] * b[j];
        }
        __syncthreads();
    }

    float4 bv = *(const float4*)(bias + n0 + tx * 4);
    #pragma unroll
    for (int i = 0; i < 8; i++) {
        int m = m0 + ty * 8 + i;
        float4 o;
        o.x = acc[i][0] + bv.x;
        o.y = acc[i][1] + bv.y;
        o.z = acc[i][2] + bv.z;
        o.w = acc[i][3] + bv.w;
        *(float4*)(C + (size_t)m * 1024 + n0 + tx * 4) = o;
    }
}

// ============================================================================
// Attention: one CTA per t. 512 threads = 16 warps.
//   scores[t, r, c] = (Q[t,r,:] . K[t,c,:]) / 8 ; softmax over c
//   O[t, r, :]      = attn[t, r, :] @ V[t, :, :]
//   w[b, t, s]      = mean_h attn[t, h*32+b, s]   (b = r % 32)
// Phase 1: K[t] in smem transposed [d][c] (pitch 516). Warp w owns rows with
//   r%32 in {2w, 2w+1}; processes 4 rows/pass; attn -> g_ATTN; w-acc in regs.
// Phase 2: V[t] in smem [c][d]; warp w handles rows [32w,32w+32), 2/pass,
//   attn rows restaged via smem; float2 over head-dim.
// ============================================================================
#define KV_PITCH 516
#define SM_KV    (64 * KV_PITCH)            // 33024 floats (>= 512*64 for V)
#define SM_QS    (16 * 256)                 // per-warp q rows (4 x 64)
#define SM_ABUF  (16 * 1024)                // per-warp 2 attn rows
#define ATT_SMEM_FLOATS (SM_KV + SM_QS + SM_ABUF)
#define ATT_SMEM_BYTES  (ATT_SMEM_FLOATS * 4)

__global__ __launch_bounds__(512, 1)
void attention_kernel(float* __restrict__ w_out)
{
    extern __shared__ float sm[];
    float* k_s  = sm;                    // phase1: [d][c] pitch 516 ; phase2: V [c][d]
    float* q_s  = sm + SM_KV;
    float* abuf = sm + SM_KV + SM_QS;

    const int t    = blockIdx.x;
    const int tid  = threadIdx.x;
    const int warp = tid >> 5;
    const int lane = tid & 31;
    const size_t tq  = (size_t)t * BH * HD;   // base into g_Q/g_K/g_V/g_O
    const size_t ta  = (size_t)t * BH * BH;   // base into g_ATTN

    // ---- load K[t] transposed into smem ----
    for (int idx4 = tid; idx4 < (BH * HD) / 4; idx4 += 512) {
        int c  = idx4 >> 4;            // row (512)
        int d4 = (idx4 & 15) * 4;      // d offset
        float4 v = *(const float4*)(g_K + tq + (size_t)c * HD + d4);
        k_s[(d4 + 0) * KV_PITCH + c] = v.x;
        k_s[(d4 + 1) * KV_PITCH + c] = v.y;
        k_s[(d4 + 2) * KV_PITCH + c] = v.z;
        k_s[(d4 + 3) * KV_PITCH + c] = v.w;
    }
    __syncthreads();

    float* qs_w = q_s + warp * 256;

    // ---- phase 1: scores + softmax + attn store + w accumulation ----
    #pragma unroll 1
    for (int bi = 0; bi < 2; bi++) {
        const int b2 = 2 * warp + bi;
        float wacc[16];
        #pragma unroll
        for (int j = 0; j < 16; j++) wacc[j] = 0.0f;

        #pragma unroll 1
        for (int g = 0; g < 4; g++) {
            // load 4 q rows: rows (g*4+r)*32 + b2
            #pragma unroll
            for (int r = 0; r < 4; r++) {
                int row = (g * 4 + r) * 32 + b2;
                qs_w[r * 64 + lane]      = g_Q[tq + (size_t)row * HD + lane];
                qs_w[r * 64 + lane + 32] = g_Q[tq + (size_t)row * HD + lane + 32];
            }
            __syncwarp();

            float acc[4][16];
            #pragma unroll
            for (int r = 0; r < 4; r++)
                #pragma unroll
                for (int j = 0; j < 16; j++) acc[r][j] = 0.0f;

            const float* kbase = k_s + lane * 16;
            #pragma unroll 2
            for (int d = 0; d < 64; d++) {
                const float* kr = kbase + d * KV_PITCH;
                float4 k0 = *(const float4*)(kr);
                float4 k1 = *(const float4*)(kr + 4);
                float4 k2 = *(const float4*)(kr + 8);
                float4 k3 = *(const float4*)(kr + 12);
                float kk[16] = {k0.x, k0.y, k0.z, k0.w, k1.x, k1.y, k1.z, k1.w,
                                k2.x, k2.y, k2.z, k2.w, k3.x, k3.y, k3.z, k3.w};
                #pragma unroll
                for (int r = 0; r < 4; r++) {
                    float q = qs_w[r * 64 + d];
                    #pragma unroll
                    for (int j = 0; j < 16; j++) acc[r][j] += q * kk[j];
                }
            }

            // softmax per row + store attn + accumulate w
            #pragma unroll
            for (int r = 0; r < 4; r++) {
                int row = (g * 4 + r) * 32 + b2;
                float mx = acc[r][0];
                #pragma unroll
                for (int j = 1; j < 16; j++) mx = fmaxf(mx, acc[r][j]);
                #pragma unroll
                for (int off = 16; off > 0; off >>= 1)
                    mx = fmaxf(mx, __shfl_xor_sync(0xffffffffu, mx, off));
                float sum = 0.0f;
                float p[16];
                #pragma unroll
                for (int j = 0; j < 16; j++) {
                    p[j] = __expf((acc[r][j] - mx) * 0.125f);
                    sum += p[j];
                }
                #pragma unroll
                for (int off = 16; off > 0; off >>= 1)
                    sum += __shfl_xor_sync(0xffffffffu, sum, off);
                float inv = 1.0f / sum;
                float* arow = g_ATTN + ta + (size_t)row * BH + lane * 16;
                #pragma unroll
                for (int q4 = 0; q4 < 4; q4++) {
                    float4 st;
                    st.x = p[q4 * 4 + 0] * inv;
                    st.y = p[q4 * 4 + 1] * inv;
                    st.z = p[q4 * 4 + 2] * inv;
                    st.w = p[q4 * 4 + 3] * inv;
                    *(float4*)(arow + q4 * 4) = st;
                    wacc[q4 * 4 + 0] += st.x;
                    wacc[q4 * 4 + 1] += st.y;
                    wacc[q4 * 4 + 2] += st.z;
                    wacc[q4 * 4 + 3] += st.w;
                }
            }
        }
        // write w[b2, t, :]  (mean over 16 heads)
        float* wrow = w_out + (size_t)b2 * (T_LEN * BH) + (size_t)t * BH + lane * 16;
        #pragma unroll
        for (int q4 = 0; q4 < 4; q4++) {
            float4 st;
            st.x = wacc[q4 * 4 + 0] * 0.0625f;
            st.y = wacc[q4 * 4 + 1] * 0.0625f;
            st.z = wacc[q4 * 4 + 2] * 0.0625f;
            st.w = wacc[q4 * 4 + 3] * 0.0625f;
            *(float4*)(wrow + q4 * 4) = st;
        }
    }

    // ---- phase 2: attn @ V ----
    __syncthreads();
    {   // load V[t] contiguous into smem [c][d]
        const float4* vsrc = (const float4*)(g_V + tq);
        float4* vdst = (float4*)k_s;
        for (int idx4 = tid; idx4 < (BH * HD) / 4; idx4 += 512)
            vdst[idx4] = vsrc[idx4];
    }
    __syncthreads();

    float* ab = abuf + warp * 1024;
    #pragma unroll 1
    for (int pg = 0; pg < 16; pg++) {
        int ra = warp * 32 + 2 * pg;
        int rb = ra + 1;
        // stage 2 attn rows into smem
        {
            const float4* sa = (const float4*)(g_ATTN + ta + (size_t)ra * BH);
            const float4* sb = (const float4*)(g_ATTN + ta + (size_t)rb * BH);
            float4* da = (float4*)ab;
            float4* db = (float4*)(ab + 512);
            #pragma unroll
            for (int q4 = 0; q4 < 4; q4++) {
                da[q4 * 32 + lane] = sa[q4 * 32 + lane];
                db[q4 * 32 + lane] = sb[q4 * 32 + lane];
            }
        }
        __syncwarp();

        float2 o0 = make_float2(0.f, 0.f);
        float2 o1 = make_float2(0.f, 0.f);
        const float* vrow = k_s + lane * 2;
        #pragma unroll 4
        for (int c = 0; c < 512; c++) {
            float2 v2 = *(const float2*)(vrow + c * 64);
            float a0 = ab[c];
            float a1 = ab[512 + c];
            o0.x += a0 * v2.x; o0.y += a0 * v2.y;
            o1.x += a1 * v2.x; o1.y += a1 * v2.y;
        }
        *(float2*)(g_O + tq + (size_t)ra * HD + lane * 2) = o0;
        *(float2*)(g_O + tq + (size_t)rb * HD + lane * 2) = o1;
        __syncwarp();
    }
}

// ============================================================================
extern "C" void kernel_launch(void* const* d_in, const int* in_sizes, int n_in,
                              void* d_out, int out_size)
{
    const float* query = (const float*)d_in[0];
    const float* key   = (const float*)d_in[1];
    const float* value = (const float*)d_in[2];
    const float* Wq = (const float*)d_in[3];
    const float* bq = (const float*)d_in[4];
    const float* Wk = (const float*)d_in[5];
    const float* bk = (const float*)d_in[6];
    const float* Wv = (const float*)d_in[7];
    const float* bv = (const float*)d_in[8];
    const float* Wo = (const float*)d_in[9];
    const float* bo = (const float*)d_in[10];

    float* out   = (float*)d_out;                          // [T,B,D] = 16777216
    float* w_out = out + (size_t)T_LEN * B_SZ * D_EMB;     // [B,T,S] =  8388608

    void *qp, *kp, *vp, *op;
    cudaGetSymbolAddress(&qp, g_Q);
    cudaGetSymbolAddress(&kp, g_K);
    cudaGetSymbolAddress(&vp, g_V);
    cudaGetSymbolAddress(&op, g_O);

    cudaFuncSetAttribute(attention_kernel,
                         cudaFuncAttributeMaxDynamicSharedMemorySize,
                         ATT_SMEM_BYTES);

    dim3 ggrid(1024 / 64, M_ROWS / 128);   // (16, 128)

    gemm_nt_kernel<1><<<ggrid, 256>>>(query, Wq, bq, (float*)qp);
    gemm_nt_kernel<0><<<ggrid, 256>>>(key,   Wk, bk, (float*)kp);
    gemm_nt_kernel<0><<<ggrid, 256>>>(value, Wv, bv, (float*)vp);

    attention_kernel<<<T_LEN, 512, ATT_SMEM_BYTES>>>(w_out);

    gemm_nt_kernel<0><<<ggrid, 256>>>((const float*)op, Wo, bo, out);
}

// round 4
// speedup vs baseline: 1.4538x; 1.4538x over previous
#include <cuda_runtime.h>
#include <cuda_bf16.h>
#include <math.h>
#include <stdint.h>

// Problem constants
#define T_LEN 512
#define B_SZ  32
#define H_N   16
#define HD    64
#define D_EMB 1024
#define BH    512
#define M_ROWS 16384       // T_LEN * B_SZ

// ---------------- device scratch (static: no allocations allowed) -----------
__device__ float g_Q[(size_t)T_LEN * BH * HD];
__device__ float g_K[(size_t)T_LEN * BH * HD];
__device__ float g_V[(size_t)T_LEN * BH * HD];
__device__ float g_O[(size_t)T_LEN * BH * HD];
__device__ float g_ATTN[(size_t)T_LEN * BH * BH];       // 536 MB
__device__ __nv_bfloat16 g_Ahi[(size_t)M_ROWS * D_EMB]; // 32 MB
__device__ __nv_bfloat16 g_Alo[(size_t)M_ROWS * D_EMB];
__device__ __nv_bfloat16 g_Whi[(size_t)D_EMB * D_EMB];  // 2 MB
__device__ __nv_bfloat16 g_Wlo[(size_t)D_EMB * D_EMB];

// ====================== helpers ==============================================
__device__ __forceinline__ uint32_t smem_to_u32(const void* p) {
    uint32_t a;
    asm("{ .reg .u64 t; cvta.to.shared.u64 t, %1; cvt.u32.u64 %0, t; }" : "=r"(a) : "l"(p));
    return a;
}

#define CP_ASYNC16(dst, src) \
    asm volatile("cp.async.cg.shared.global [%0], [%1], 16;" :: "r"((uint32_t)(dst)), "l"(src) : "memory")

__device__ __forceinline__ void ldsm_x4(uint32_t* r, uint32_t addr) {
    asm volatile("ldmatrix.sync.aligned.m8n8.x4.shared.b16 {%0,%1,%2,%3}, [%4];"
        : "=r"(r[0]), "=r"(r[1]), "=r"(r[2]), "=r"(r[3]) : "r"(addr));
}

__device__ __forceinline__ void mma_bf16(float* d, const uint32_t* a, const uint32_t* b) {
    asm volatile(
        "mma.sync.aligned.m16n8k16.row.col.f32.bf16.bf16.f32 "
        "{%0,%1,%2,%3}, {%4,%5,%6,%7}, {%8,%9}, {%0,%1,%2,%3};"
        : "+f"(d[0]), "+f"(d[1]), "+f"(d[2]), "+f"(d[3])
        : "r"(a[0]), "r"(a[1]), "r"(a[2]), "r"(a[3]), "r"(b[0]), "r"(b[1]));
}

// ====================== fp32 -> bf16 hi/lo split ============================
// grid = #rows, block = 256. qmode=1: row m reads query[b=m&31][t=m>>5][*].
__global__ __launch_bounds__(256)
void split_kernel(const float* __restrict__ X, __nv_bfloat16* __restrict__ hi,
                  __nv_bfloat16* __restrict__ lo, int qmode)
{
    int m = blockIdx.x;
    size_t src_off = qmode ? ((size_t)(m & 31) * 512 + (size_t)(m >> 5)) * 1024
                           : (size_t)m * 1024;
    int c = threadIdx.x * 4;
    float4 v = *(const float4*)(X + src_off + c);
    __nv_bfloat16 h0 = __float2bfloat16(v.x);
    __nv_bfloat16 h1 = __float2bfloat16(v.y);
    __nv_bfloat16 h2 = __float2bfloat16(v.z);
    __nv_bfloat16 h3 = __float2bfloat16(v.w);
    __nv_bfloat16 l0 = __float2bfloat16(v.x - __bfloat162float(h0));
    __nv_bfloat16 l1 = __float2bfloat16(v.y - __bfloat162float(h1));
    __nv_bfloat16 l2 = __float2bfloat16(v.z - __bfloat162float(h2));
    __nv_bfloat16 l3 = __float2bfloat16(v.w - __bfloat162float(h3));
    size_t dst = (size_t)m * 1024 + c;
    __nv_bfloat162 hp0 = __halves2bfloat162(h0, h1);
    __nv_bfloat162 hp1 = __halves2bfloat162(h2, h3);
    __nv_bfloat162 lp0 = __halves2bfloat162(l0, l1);
    __nv_bfloat162 lp1 = __halves2bfloat162(l2, l3);
    uint2 hw, lw;
    hw.x = *(uint32_t*)&hp0; hw.y = *(uint32_t*)&hp1;
    lw.x = *(uint32_t*)&lp0; lw.y = *(uint32_t*)&lp1;
    *(uint2*)(hi + dst) = hw;
    *(uint2*)(lo + dst) = lw;
}

// ====================== mma.sync split-bf16 GEMM =============================
// C[M,1024] = A@W^T + bias via Ahi.Whi + Ahi.Wlo + Alo.Whi (fp32 accum).
// CTA tile 128x128, BK=32, 8 warps (2m x 4n), warp tile 64x32, 2-stage cp.async.
#define GK_PITCH   80                       // 64B data + 16B pad: conflict-free
#define GK_TILE_B  (128 * GK_PITCH)         // 10240 B
#define GK_STAGE_B (4 * GK_TILE_B)          // Ahi | Alo | Whi | Wlo
#define GK_SMEM    (2 * GK_STAGE_B)         // 81920 B

__global__ __launch_bounds__(256, 1)
void gemm_mma_kernel(const __nv_bfloat16* __restrict__ Ahi, const __nv_bfloat16* __restrict__ Alo,
                     const __nv_bfloat16* __restrict__ Whi, const __nv_bfloat16* __restrict__ Wlo,
                     const float* __restrict__ bias, float* __restrict__ C)
{
    extern __shared__ char smem[];
    const uint32_t sb = smem_to_u32(smem);
    const int tid  = threadIdx.x;
    const int lane = tid & 31;
    const int warp = tid >> 5;
    const int warp_m = warp >> 2;           // 0..1
    const int warp_n = warp & 3;            // 0..3
    const int m0 = blockIdx.y * 128;
    const int n0 = blockIdx.x * 128;

    const char* gA  = (const char*)(Ahi + (size_t)m0 * 1024);
    const char* gAl = (const char*)(Alo + (size_t)m0 * 1024);
    const char* gW  = (const char*)(Whi + (size_t)n0 * 1024);
    const char* gWl = (const char*)(Wlo + (size_t)n0 * 1024);

#define LOAD_STAGE(c) do { \
        uint32_t st_ = sb + ((c) & 1) * GK_STAGE_B; \
        int k0b_ = (c) * 64; \
        _Pragma("unroll") \
        for (int i_ = 0; i_ < 2; i_++) { \
            int idx_ = i_ * 256 + tid; \
            int r_ = idx_ >> 2, ch_ = idx_ & 3; \
            uint32_t so_ = (uint32_t)(r_ * GK_PITCH + ch_ * 16); \
            size_t go_ = (size_t)r_ * 2048 + k0b_ + ch_ * 16; \
            CP_ASYNC16(st_ + so_,                   gA  + go_); \
            CP_ASYNC16(st_ + GK_TILE_B + so_,       gAl + go_); \
            CP_ASYNC16(st_ + 2 * GK_TILE_B + so_,   gW  + go_); \
            CP_ASYNC16(st_ + 3 * GK_TILE_B + so_,   gWl + go_); \
        } \
        asm volatile("cp.async.commit_group;" ::: "memory"); \
    } while (0)

    // ldmatrix per-thread base offsets
    const int j  = lane >> 3;           // matrix index 0..3
    const int r8 = lane & 7;
    const uint32_t aBase = (uint32_t)((warp_m * 64 + (j & 1) * 8 + r8) * GK_PITCH + (j >> 1) * 16);
    const uint32_t bBase = (uint32_t)((warp_n * 32 + (lane >> 4) * 8 + r8) * GK_PITCH + ((lane >> 3) & 1) * 16);

    float acc[4][4][4];
    #pragma unroll
    for (int mi = 0; mi < 4; mi++)
        #pragma unroll
        for (int ni = 0; ni < 4; ni++)
            #pragma unroll
            for (int q = 0; q < 4; q++) acc[mi][ni][q] = 0.0f;

    LOAD_STAGE(0);

    #pragma unroll 1
    for (int c = 0; c < 32; c++) {
        if (c + 1 < 32) {
            LOAD_STAGE(c + 1);
            asm volatile("cp.async.wait_group 1;" ::: "memory");
        } else {
            asm volatile("cp.async.wait_group 0;" ::: "memory");
        }
        __syncthreads();
        uint32_t st = sb + (c & 1) * GK_STAGE_B;

        #pragma unroll
        for (int ks = 0; ks < 2; ks++) {
            uint32_t ah[4][4], al[4][4], wh[2][4], wl[2][4];
            #pragma unroll
            for (int mi = 0; mi < 4; mi++) {
                uint32_t ao = st + aBase + mi * 16 * GK_PITCH + ks * 32;
                ldsm_x4(ah[mi], ao);
                ldsm_x4(al[mi], ao + GK_TILE_B);
            }
            #pragma unroll
            for (int p = 0; p < 2; p++) {
                uint32_t bo = st + 2 * GK_TILE_B + bBase + p * 16 * GK_PITCH + ks * 32;
                ldsm_x4(wh[p], bo);
                ldsm_x4(wl[p], bo + GK_TILE_B);
            }
            #pragma unroll
            for (int mi = 0; mi < 4; mi++)
                #pragma unroll
                for (int ni = 0; ni < 4; ni++) {
                    const uint32_t* bh = &wh[ni >> 1][(ni & 1) * 2];
                    const uint32_t* bl = &wl[ni >> 1][(ni & 1) * 2];
                    mma_bf16(acc[mi][ni], ah[mi], bh);
                    mma_bf16(acc[mi][ni], ah[mi], bl);
                    mma_bf16(acc[mi][ni], al[mi], bh);
                }
        }
        __syncthreads();
    }

    // epilogue: bias add + store
    #pragma unroll
    for (int mi = 0; mi < 4; mi++) {
        int r0 = m0 + warp_m * 64 + mi * 16 + (lane >> 2);
        #pragma unroll
        for (int ni = 0; ni < 4; ni++) {
            int col = n0 + warp_n * 32 + ni * 8 + (lane & 3) * 2;
            float bx = bias[col], by = bias[col + 1];
            float2 v0 = make_float2(acc[mi][ni][0] + bx, acc[mi][ni][1] + by);
            float2 v1 = make_float2(acc[mi][ni][2] + bx, acc[mi][ni][3] + by);
            *(float2*)(C + (size_t)r0 * 1024 + col) = v0;
            *(float2*)(C + (size_t)(r0 + 8) * 1024 + col) = v1;
        }
    }
#undef LOAD_STAGE
}

// ====================== attention (unchanged from R1) ========================
#define KV_PITCH 516
#define SM_KV    (64 * KV_PITCH)
#define SM_QS    (16 * 256)
#define SM_ABUF  (16 * 1024)
#define ATT_SMEM_FLOATS (SM_KV + SM_QS + SM_ABUF)
#define ATT_SMEM_BYTES  (ATT_SMEM_FLOATS * 4)

__global__ __launch_bounds__(512, 1)
void attention_kernel(float* __restrict__ w_out)
{
    extern __shared__ float sm[];
    float* k_s  = sm;
    float* q_s  = sm + SM_KV;
    float* abuf = sm + SM_KV + SM_QS;

    const int t    = blockIdx.x;
    const int tid  = threadIdx.x;
    const int warp = tid >> 5;
    const int lane = tid & 31;
    const size_t tq  = (size_t)t * BH * HD;
    const size_t ta  = (size_t)t * BH * BH;

    for (int idx4 = tid; idx4 < (BH * HD) / 4; idx4 += 512) {
        int c  = idx4 >> 4;
        int d4 = (idx4 & 15) * 4;
        float4 v = *(const float4*)(g_K + tq + (size_t)c * HD + d4);
        k_s[(d4 + 0) * KV_PITCH + c] = v.x;
        k_s[(d4 + 1) * KV_PITCH + c] = v.y;
        k_s[(d4 + 2) * KV_PITCH + c] = v.z;
        k_s[(d4 + 3) * KV_PITCH + c] = v.w;
    }
    __syncthreads();

    float* qs_w = q_s + warp * 256;

    #pragma unroll 1
    for (int bi = 0; bi < 2; bi++) {
        const int b2 = 2 * warp + bi;
        float wacc[16];
        #pragma unroll
        for (int jj = 0; jj < 16; jj++) wacc[jj] = 0.0f;

        #pragma unroll 1
        for (int g = 0; g < 4; g++) {
            #pragma unroll
            for (int r = 0; r < 4; r++) {
                int row = (g * 4 + r) * 32 + b2;
                qs_w[r * 64 + lane]      = g_Q[tq + (size_t)row * HD + lane];
                qs_w[r * 64 + lane + 32] = g_Q[tq + (size_t)row * HD + lane + 32];
            }
            __syncwarp();

            float acc[4][16];
            #pragma unroll
            for (int r = 0; r < 4; r++)
                #pragma unroll
                for (int jj = 0; jj < 16; jj++) acc[r][jj] = 0.0f;

            const float* kbase = k_s + lane * 16;
            #pragma unroll 2
            for (int d = 0; d < 64; d++) {
                const float* kr = kbase + d * KV_PITCH;
                float4 k0 = *(const float4*)(kr);
                float4 k1 = *(const float4*)(kr + 4);
                float4 k2 = *(const float4*)(kr + 8);
                float4 k3 = *(const float4*)(kr + 12);
                float kk[16] = {k0.x, k0.y, k0.z, k0.w, k1.x, k1.y, k1.z, k1.w,
                                k2.x, k2.y, k2.z, k2.w, k3.x, k3.y, k3.z, k3.w};
                #pragma unroll
                for (int r = 0; r < 4; r++) {
                    float q = qs_w[r * 64 + d];
                    #pragma unroll
                    for (int jj = 0; jj < 16; jj++) acc[r][jj] += q * kk[jj];
                }
            }

            #pragma unroll
            for (int r = 0; r < 4; r++) {
                int row = (g * 4 + r) * 32 + b2;
                float mx = acc[r][0];
                #pragma unroll
                for (int jj = 1; jj < 16; jj++) mx = fmaxf(mx, acc[r][jj]);
                #pragma unroll
                for (int off = 16; off > 0; off >>= 1)
                    mx = fmaxf(mx, __shfl_xor_sync(0xffffffffu, mx, off));
                float sum = 0.0f;
                float p[16];
                #pragma unroll
                for (int jj = 0; jj < 16; jj++) {
                    p[jj] = __expf((acc[r][jj] - mx) * 0.125f);
                    sum += p[jj];
                }
                #pragma unroll
                for (int off = 16; off > 0; off >>= 1)
                    sum += __shfl_xor_sync(0xffffffffu, sum, off);
                float inv = 1.0f / sum;
                float* arow = g_ATTN + ta + (size_t)row * BH + lane * 16;
                #pragma unroll
                for (int q4 = 0; q4 < 4; q4++) {
                    float4 st;
                    st.x = p[q4 * 4 + 0] * inv;
                    st.y = p[q4 * 4 + 1] * inv;
                    st.z = p[q4 * 4 + 2] * inv;
                    st.w = p[q4 * 4 + 3] * inv;
                    *(float4*)(arow + q4 * 4) = st;
                    wacc[q4 * 4 + 0] += st.x;
                    wacc[q4 * 4 + 1] += st.y;
                    wacc[q4 * 4 + 2] += st.z;
                    wacc[q4 * 4 + 3] += st.w;
                }
            }
        }
        float* wrow = w_out + (size_t)b2 * (T_LEN * BH) + (size_t)t * BH + lane * 16;
        #pragma unroll
        for (int q4 = 0; q4 < 4; q4++) {
            float4 st;
            st.x = wacc[q4 * 4 + 0] * 0.0625f;
            st.y = wacc[q4 * 4 + 1] * 0.0625f;
            st.z = wacc[q4 * 4 + 2] * 0.0625f;
            st.w = wacc[q4 * 4 + 3] * 0.0625f;
            *(float4*)(wrow + q4 * 4) = st;
        }
    }

    __syncthreads();
    {
        const float4* vsrc = (const float4*)(g_V + tq);
        float4* vdst = (float4*)k_s;
        for (int idx4 = tid; idx4 < (BH * HD) / 4; idx4 += 512)
            vdst[idx4] = vsrc[idx4];
    }
    __syncthreads();

    float* ab = abuf + warp * 1024;
    #pragma unroll 1
    for (int pg = 0; pg < 16; pg++) {
        int ra = warp * 32 + 2 * pg;
        int rb = ra + 1;
        {
            const float4* sa  = (const float4*)(g_ATTN + ta + (size_t)ra * BH);
            const float4* sb2 = (const float4*)(g_ATTN + ta + (size_t)rb * BH);
            float4* da = (float4*)ab;
            float4* db = (float4*)(ab + 512);
            #pragma unroll
            for (int q4 = 0; q4 < 4; q4++) {
                da[q4 * 32 + lane] = sa[q4 * 32 + lane];
                db[q4 * 32 + lane] = sb2[q4 * 32 + lane];
            }
        }
        __syncwarp();

        float2 o0 = make_float2(0.f, 0.f);
        float2 o1 = make_float2(0.f, 0.f);
        const float* vrow = k_s + lane * 2;
        #pragma unroll 4
        for (int c = 0; c < 512; c++) {
            float2 v2 = *(const float2*)(vrow + c * 64);
            float a0 = ab[c];
            float a1 = ab[512 + c];
            o0.x += a0 * v2.x; o0.y += a0 * v2.y;
            o1.x += a1 * v2.x; o1.y += a1 * v2.y;
        }
        *(float2*)(g_O + tq + (size_t)ra * HD + lane * 2) = o0;
        *(float2*)(g_O + tq + (size_t)rb * HD + lane * 2) = o1;
        __syncwarp();
    }
}

// ============================================================================
extern "C" void kernel_launch(void* const* d_in, const int* in_sizes, int n_in,
                              void* d_out, int out_size)
{
    const float* query = (const float*)d_in[0];
    const float* key   = (const float*)d_in[1];
    const float* value = (const float*)d_in[2];
    const float* Wq = (const float*)d_in[3];
    const float* bq = (const float*)d_in[4];
    const float* Wk = (const float*)d_in[5];
    const float* bk = (const float*)d_in[6];
    const float* Wv = (const float*)d_in[7];
    const float* bv = (const float*)d_in[8];
    const float* Wo = (const float*)d_in[9];
    const float* bo = (const float*)d_in[10];

    float* out   = (float*)d_out;
    float* w_out = out + (size_t)T_LEN * B_SZ * D_EMB;

    void *qp, *kp, *vp, *op, *ahp, *alp, *whp, *wlp;
    cudaGetSymbolAddress(&qp, g_Q);
    cudaGetSymbolAddress(&kp, g_K);
    cudaGetSymbolAddress(&vp, g_V);
    cudaGetSymbolAddress(&op, g_O);
    cudaGetSymbolAddress(&ahp, g_Ahi);
    cudaGetSymbolAddress(&alp, g_Alo);
    cudaGetSymbolAddress(&whp, g_Whi);
    cudaGetSymbolAddress(&wlp, g_Wlo);
    __nv_bfloat16* Ahi = (__nv_bfloat16*)ahp;
    __nv_bfloat16* Alo = (__nv_bfloat16*)alp;
    __nv_bfloat16* Whi = (__nv_bfloat16*)whp;
    __nv_bfloat16* Wlo = (__nv_bfloat16*)wlp;

    cudaFuncSetAttribute(attention_kernel,
                         cudaFuncAttributeMaxDynamicSharedMemorySize, ATT_SMEM_BYTES);
    cudaFuncSetAttribute(gemm_mma_kernel,
                         cudaFuncAttributeMaxDynamicSharedMemorySize, GK_SMEM);

    dim3 ggrid(D_EMB / 128, M_ROWS / 128);   // (8, 128)

    // Q projection (with [B,T,D] permute folded into split)
    split_kernel<<<M_ROWS, 256>>>(query, Ahi, Alo, 1);
    split_kernel<<<D_EMB, 256>>>(Wq, Whi, Wlo, 0);
    gemm_mma_kernel<<<ggrid, 256, GK_SMEM>>>(Ahi, Alo, Whi, Wlo, bq, (float*)qp);

    // K projection
    split_kernel<<<M_ROWS, 256>>>(key, Ahi, Alo, 0);
    split_kernel<<<D_EMB, 256>>>(Wk, Whi, Wlo, 0);
    gemm_mma_kernel<<<ggrid, 256, GK_SMEM>>>(Ahi, Alo, Whi, Wlo, bk, (float*)kp);

    // V projection
    split_kernel<<<M_ROWS, 256>>>(value, Ahi, Alo, 0);
    split_kernel<<<D_EMB, 256>>>(Wv, Whi, Wlo, 0);
    gemm_mma_kernel<<<ggrid, 256, GK_SMEM>>>(Ahi, Alo, Whi, Wlo, bv, (float*)vp);

    attention_kernel<<<T_LEN, 512, ATT_SMEM_BYTES>>>(w_out);

    // output projection
    split_kernel<<<M_ROWS, 256>>>((const float*)op, Ahi, Alo, 0);
    split_kernel<<<D_EMB, 256>>>(Wo, Whi, Wlo, 0);
    gemm_mma_kernel<<<ggrid, 256, GK_SMEM>>>(Ahi, Alo, Whi, Wlo, bo, out);
}